// round 2
// baseline (speedup 1.0000x reference)
#include <cuda_runtime.h>

// Problem shape (fixed by the dataset): B=256, N=65536.
// in:  I1, I2 as (B, N, 2) fp32 interleaved complex
// out: (B, 2N) fp32 where out[b, 0..N) = real[b,:], out[b, N..2N) = imag[b,:]

static constexpr int B_DIM = 256;
static constexpr int N_DIM = 65536;          // power of two -> shift/mask decode
static constexpr int N_SHIFT = 16;           // log2(N_DIM)
static constexpr unsigned N_MASK = N_DIM - 1;

// 8 complex elements per thread: 4x float4 loads per input (front-batched,
// MLP=8 outstanding LDG.128), streaming cache hints (zero reuse workload).
__global__ void __launch_bounds__(256, 8)
prod_cmp_kernel(const float4* __restrict__ in1,
                const float4* __restrict__ in2,
                float4* __restrict__ out)
{
    const long long tid = (long long)blockIdx.x * blockDim.x + threadIdx.x;
    const long long cbase = tid * 8;                 // first complex index handled

    const unsigned b = (unsigned)(cbase >> N_SHIFT); // batch
    const unsigned k = (unsigned)(cbase & N_MASK);   // position within row (mult of 8)

    const long long fin = cbase >> 1;                // float4 index = tid*4

    // Front-batch all 8 loads (evict-streaming: no reuse anywhere)
    float4 a0 = __ldcs(&in1[fin + 0]);
    float4 a1 = __ldcs(&in1[fin + 1]);
    float4 a2 = __ldcs(&in1[fin + 2]);
    float4 a3 = __ldcs(&in1[fin + 3]);
    float4 c0 = __ldcs(&in2[fin + 0]);
    float4 c1 = __ldcs(&in2[fin + 1]);
    float4 c2 = __ldcs(&in2[fin + 2]);
    float4 c3 = __ldcs(&in2[fin + 3]);

    float4 re0, re1, im0, im1;
    re0.x = fmaf(a0.x, c0.x, -a0.y * c0.y);
    im0.x = fmaf(a0.y, c0.x,  a0.x * c0.y);
    re0.y = fmaf(a0.z, c0.z, -a0.w * c0.w);
    im0.y = fmaf(a0.w, c0.z,  a0.z * c0.w);
    re0.z = fmaf(a1.x, c1.x, -a1.y * c1.y);
    im0.z = fmaf(a1.y, c1.x,  a1.x * c1.y);
    re0.w = fmaf(a1.z, c1.z, -a1.w * c1.w);
    im0.w = fmaf(a1.w, c1.z,  a1.z * c1.w);

    re1.x = fmaf(a2.x, c2.x, -a2.y * c2.y);
    im1.x = fmaf(a2.y, c2.x,  a2.x * c2.y);
    re1.y = fmaf(a2.z, c2.z, -a2.w * c2.w);
    im1.y = fmaf(a2.w, c2.z,  a2.z * c2.w);
    re1.z = fmaf(a3.x, c3.x, -a3.y * c3.y);
    im1.z = fmaf(a3.y, c3.x,  a3.x * c3.y);
    re1.w = fmaf(a3.z, c3.z, -a3.w * c3.w);
    im1.w = fmaf(a3.w, c3.z,  a3.z * c3.w);

    // Output row b: reals at floats [b*2N + k .. +8), imags at [b*2N + N + k .. +8)
    const long long row_f4 = (long long)b * ((2 * N_DIM) / 4);
    const long long kf4 = (k >> 2);
    __stcs(&out[row_f4 + kf4 + 0], re0);
    __stcs(&out[row_f4 + kf4 + 1], re1);
    __stcs(&out[row_f4 + (N_DIM >> 2) + kf4 + 0], im0);
    __stcs(&out[row_f4 + (N_DIM >> 2) + kf4 + 1], im1);
}

extern "C" void kernel_launch(void* const* d_in, const int* in_sizes, int n_in,
                              void* d_out, int out_size)
{
    const float4* in1 = (const float4*)d_in[0];
    const float4* in2 = (const float4*)d_in[1];
    float4* out = (float4*)d_out;

    // total complex elements = B*N = 16,777,216; 8 per thread
    const long long total_threads = (long long)B_DIM * N_DIM / 8; // 2,097,152
    const int threads = 256;
    const int blocks = (int)(total_threads / threads);            // 8192

    prod_cmp_kernel<<<blocks, threads>>>(in1, in2, out);
}

// round 3
// speedup vs baseline: 1.0801x; 1.0801x over previous
#include <cuda_runtime.h>

// Problem shape (fixed by the dataset): B=256, N=65536.
// in:  I1, I2 as (B, N, 2) fp32 interleaved complex
// out: (B, 2N) fp32 where out[b, 0..N) = real[b,:], out[b, N..2N) = imag[b,:]
//
// R1 config (4 complex/thread, grid 16384x256, plain loads) measured
// 52.3us kernel / 85% DRAM. Single delta this round: streaming stores.

static constexpr int B_DIM = 256;
static constexpr int N_DIM = 65536;          // power of two -> shift/mask decode
static constexpr int N_SHIFT = 16;           // log2(N_DIM)
static constexpr unsigned N_MASK = N_DIM - 1;

__global__ void __launch_bounds__(256, 8)
prod_cmp_kernel(const float4* __restrict__ in1,
                const float4* __restrict__ in2,
                float4* __restrict__ out)
{
    // Each thread handles 4 complex elements = 2 float4 loads per input,
    // 1 float4 real store + 1 float4 imag store.
    const long long tid = (long long)blockIdx.x * blockDim.x + threadIdx.x;
    const long long cbase = tid * 4;                 // first complex index handled

    const unsigned b = (unsigned)(cbase >> N_SHIFT); // batch
    const unsigned k = (unsigned)(cbase & N_MASK);   // position within row (mult of 4)

    const long long fin = cbase >> 1;                // float4 index = tid*2
    const float4 a0 = in1[fin];
    const float4 a1 = in1[fin + 1];
    const float4 b0 = in2[fin];
    const float4 b1 = in2[fin + 1];

    float4 re, im;
    re.x = fmaf(a0.x, b0.x, -a0.y * b0.y);
    im.x = fmaf(a0.y, b0.x,  a0.x * b0.y);
    re.y = fmaf(a0.z, b0.z, -a0.w * b0.w);
    im.y = fmaf(a0.w, b0.z,  a0.z * b0.w);
    re.z = fmaf(a1.x, b1.x, -a1.y * b1.y);
    im.z = fmaf(a1.y, b1.x,  a1.x * b1.y);
    re.w = fmaf(a1.z, b1.z, -a1.w * b1.w);
    im.w = fmaf(a1.w, b1.z,  a1.z * b1.w);

    // Output row b has 2N floats: reals at [b*2N + k], imags at [b*2N + N + k].
    const long long row_f4 = (long long)b * ((2 * N_DIM) / 4);
    __stcs(&out[row_f4 + (k >> 2)], re);
    __stcs(&out[row_f4 + (N_DIM >> 2) + (k >> 2)], im);
}

extern "C" void kernel_launch(void* const* d_in, const int* in_sizes, int n_in,
                              void* d_out, int out_size)
{
    const float4* in1 = (const float4*)d_in[0];
    const float4* in2 = (const float4*)d_in[1];
    float4* out = (float4*)d_out;

    // total complex elements = B*N = 16,777,216; 4 per thread
    const long long total_threads = (long long)B_DIM * N_DIM / 4; // 4,194,304
    const int threads = 256;
    const int blocks = (int)(total_threads / threads);            // 16384

    prod_cmp_kernel<<<blocks, threads>>>(in1, in2, out);
}